// round 16
// baseline (speedup 1.0000x reference)
#include <cuda_runtime.h>
#include <cuda_bf16.h>
#include <cstdint>

// ---------------- problem constants ----------------
#define NLAYERS 4
#define BATCH   8
#define SEQ     512
#define DMODEL  512
#define ED      1024
#define DSTATE  16
#define DTRANK  32
#define DCONV   4
#define TOK     (BATCH*SEQ)   // 4096
#define KSPLIT  8             // x_proj K-slices

typedef __nv_bfloat16 bf16;

// ---------------- scratch (device globals; no allocation) ----------------
__device__ __align__(16) float g_xbuf [TOK*DMODEL];     // residual stream
__device__ __align__(16) float g_xz   [TOK*2*ED];       // in_proj out (xb|z)
__device__ __align__(16) float g_xc   [TOK*ED];         // conv+silu (fp32 for scan)
__device__ __align__(16) float g_dbc  [TOK*64];         // x_proj out (dt|B|C)
__device__ __align__(16) float g_dbcp [KSPLIT*TOK*64];  // x_proj split-K partials
__device__ __align__(16) float g_delta[TOK*ED];         // softplus(dt_proj)

// bf16 split activations
__device__ __align__(16) bf16 g_xn_h[TOK*DMODEL],  g_xn_l[TOK*DMODEL];
__device__ __align__(16) bf16 g_xc_h[TOK*ED],      g_xc_l[TOK*ED];
__device__ __align__(16) bf16 g_y_h [TOK*ED],      g_y_l [TOK*ED];
__device__ __align__(16) bf16 g_dt_h[TOK*DTRANK],  g_dt_l[TOK*DTRANK];

// bf16 split weights
__device__ __align__(16) bf16 g_inw_h[NLAYERS*2*ED*DMODEL], g_inw_l[NLAYERS*2*ED*DMODEL];
__device__ __align__(16) bf16 g_outw_h[NLAYERS*DMODEL*ED],  g_outw_l[NLAYERS*DMODEL*ED];
__device__ __align__(16) bf16 g_xpw_h[NLAYERS*64*ED],       g_xpw_l[NLAYERS*64*ED];
__device__ __align__(16) bf16 g_dtw_h[NLAYERS*ED*DTRANK],   g_dtw_l[NLAYERS*ED*DTRANK];

// ---------------- HMMA m16n8k16 bf16 + ldmatrix ----------------
__device__ __forceinline__ void mma16816(float* c, const uint32_t* a, const uint32_t* b) {
    asm volatile(
        "mma.sync.aligned.m16n8k16.row.col.f32.bf16.bf16.f32 "
        "{%0,%1,%2,%3}, {%4,%5,%6,%7}, {%8,%9}, {%0,%1,%2,%3};"
        : "+f"(c[0]), "+f"(c[1]), "+f"(c[2]), "+f"(c[3])
        : "r"(a[0]), "r"(a[1]), "r"(a[2]), "r"(a[3]), "r"(b[0]), "r"(b[1]));
}
__device__ __forceinline__ void ldsm_x4(uint32_t* r, uint32_t addr) {
    asm volatile("ldmatrix.sync.aligned.m8n8.x4.shared.b16 {%0,%1,%2,%3}, [%4];"
        : "=r"(r[0]), "=r"(r[1]), "=r"(r[2]), "=r"(r[3]) : "r"(addr));
}
__device__ __forceinline__ void ldsm_x2(uint32_t* r, uint32_t addr) {
    asm volatile("ldmatrix.sync.aligned.m8n8.x2.shared.b16 {%0,%1}, [%2];"
        : "=r"(r[0]), "=r"(r[1]) : "r"(addr));
}
__device__ __forceinline__ void cp16(uint32_t smem_dst, const void* gsrc) {
    asm volatile("cp.async.cg.shared.global [%0], [%1], 16;" :: "r"(smem_dst), "l"(gsrc));
}
#define CP_COMMIT() asm volatile("cp.async.commit_group;" ::: "memory")
#define CP_WAIT(N)  asm volatile("cp.async.wait_group %0;" :: "n"(N) : "memory")

// ---------------- split-bf16 HMMA GEMM, 2-stage cp.async, ldmatrix ----------------
// C[M=4096, N](fp32) (+=) [Ah+Al][M,K_total] * [Bh+Bl][N,K_total]^T
// blockIdx.z = K-slice (slice length = K param); C advances czs per slice.
// EPI: 0 store, 1 softplus(acc+bias), 2 residual +=
#define SPAD 40
#define ASZ  (128*SPAD)
#define BSZ  (64*SPAD)
#define STG  (2*ASZ + 2*BSZ)
#define NSTG 2
#define GSMEM (NSTG*STG*2)           // 61440 bytes -> 3 CTAs/SM (with <=85 regs)

template<int EPI>
__global__ void __launch_bounds__(256, 3) hmma_gemm(
    const bf16* __restrict__ Ah, const bf16* __restrict__ Al, int lda,
    const bf16* __restrict__ Bh, const bf16* __restrict__ Bl, int ldb,
    float* __restrict__ C, int ldc, int K, long czs,
    const float* __restrict__ bias)
{
    extern __shared__ bf16 sm[];

    const int tid = threadIdx.x;
    const int wid = tid >> 5, lid = tid & 31;
    const int t = lid & 3;
    const int wm = wid >> 1, wn = wid & 1;
    const int mb = blockIdx.y * 128;
    const int nb = blockIdx.x * 64;
    const int koff = blockIdx.z * K;
    C += (long)blockIdx.z * czs;

    const int arow = tid >> 2, aseg = tid & 3;
    const int a_r = wm*32 + (lid & 15);
    const int a_c = (lid >> 4) * 8;
    const int b_r = wn*32 + (lid & 7);
    const int b_c = ((lid >> 3) & 1) * 8;

    const uint32_t smbase = (uint32_t)__cvta_generic_to_shared(sm);

    float c[2][4][4];
#pragma unroll
    for (int mi = 0; mi < 2; mi++)
#pragma unroll
        for (int ni = 0; ni < 4; ni++)
#pragma unroll
            for (int k = 0; k < 4; k++) c[mi][ni][k] = 0.f;

    const int nch = K >> 5;

    auto load_stage = [&](int ch, int st) {
        const int k0 = koff + (ch << 5);
        const uint32_t s0 = smbase + (uint32_t)(st * STG) * 2u;
#pragma unroll
        for (int i = 0; i < 2; i++) {
            const int row = arow + i*64;
            const uint32_t d = s0 + (uint32_t)(row*SPAD + aseg*8) * 2u;
            const long gi = (long)(mb + row) * lda + k0 + aseg*8;
            cp16(d,            Ah + gi);
            cp16(d + ASZ*2u,   Al + gi);
        }
        {
            const uint32_t d = s0 + (uint32_t)(2*ASZ + arow*SPAD + aseg*8) * 2u;
            const long gi = (long)(nb + arow) * ldb + koff + (ch << 5) + aseg*8;
            cp16(d,            Bh + gi);
            cp16(d + BSZ*2u,   Bl + gi);
        }
    };

    load_stage(0, 0);
    CP_COMMIT();

    for (int ch = 0; ch < nch; ch++) {
        const int st = ch & 1;
        if (ch + 1 < nch) {
            load_stage(ch + 1, st ^ 1);
            CP_COMMIT();
            CP_WAIT(1);
        } else {
            CP_WAIT(0);
        }
        __syncthreads();

        const uint32_t sA_h = smbase + (uint32_t)(st * STG) * 2u;
        const uint32_t sA_l = sA_h + ASZ*2u;
        const uint32_t sB_h = sA_h + 2u*ASZ*2u;
        const uint32_t sB_l = sB_h + BSZ*2u;

#pragma unroll
        for (int kk = 0; kk < 2; kk++) {
            const int kb = kk * 16;
            uint32_t ah[2][4], al[2][4], bh[4][2], bl[4][2];
#pragma unroll
            for (int mi = 0; mi < 2; mi++) {
                const uint32_t off = (uint32_t)((a_r + mi*16)*SPAD + kb + a_c) * 2u;
                ldsm_x4(ah[mi], sA_h + off);
                ldsm_x4(al[mi], sA_l + off);
            }
#pragma unroll
            for (int ni = 0; ni < 4; ni++) {
                const uint32_t off = (uint32_t)((b_r + ni*8)*SPAD + kb + b_c) * 2u;
                ldsm_x2(bh[ni], sB_h + off);
                ldsm_x2(bl[ni], sB_l + off);
            }
#pragma unroll
            for (int mi = 0; mi < 2; mi++)
#pragma unroll
                for (int ni = 0; ni < 4; ni++) {
                    mma16816(c[mi][ni], ah[mi], bh[ni]);
                    mma16816(c[mi][ni], ah[mi], bl[ni]);
                    mma16816(c[mi][ni], al[mi], bh[ni]);
                }
        }
        __syncthreads();
    }

    // ---- epilogue ----
    const int g = lid >> 2;
#pragma unroll
    for (int mi = 0; mi < 2; mi++) {
        const int row0 = mb + wm*32 + mi*16 + g;
#pragma unroll
        for (int ni = 0; ni < 4; ni++) {
            const int col = nb + wn*32 + ni*8 + 2*t;
#pragma unroll
            for (int h = 0; h < 2; h++) {
                float v0 = c[mi][ni][2*h + 0];
                float v1 = c[mi][ni][2*h + 1];
                const int row = row0 + h*8;
                float* Cr = C + (long)row * ldc + col;
                if (EPI == 1) {
                    v0 += __ldg(&bias[col + 0]);
                    v1 += __ldg(&bias[col + 1]);
                    v0 = fmaxf(v0, 0.f) + log1pf(__expf(-fabsf(v0)));
                    v1 = fmaxf(v1, 0.f) + log1pf(__expf(-fabsf(v1)));
                } else if (EPI == 2) {
                    const float2 old = *(const float2*)Cr;
                    v0 += old.x; v1 += old.y;
                }
                *(float2*)Cr = make_float2(v0, v1);
            }
        }
    }
}

// ---------------- fp32 -> bf16 hi/lo split ----------------
__device__ __forceinline__ void split1(float v, bf16* h, bf16* l, long i) {
    const bf16 hv = __float2bfloat16(v);
    h[i] = hv;
    l[i] = __float2bfloat16(v - __bfloat162float(hv));
}
// in_proj weights converter (kernel 0)
__global__ void cvt_inw(const float* __restrict__ iw) {
    const int i = blockIdx.x * 256 + threadIdx.x;
    if (i < NLAYERS*2*ED*DMODEL) split1(iw[i], g_inw_h, g_inw_l, i);
}
// remaining weights converter (kernel 1)
__global__ void cvt_rest(const float* __restrict__ ow, const float* __restrict__ xw,
                         const float* __restrict__ dw) {
    const int n_out = NLAYERS*DMODEL*ED;
    const int n_xp  = NLAYERS*64*ED;
    const int n_dt  = NLAYERS*ED*DTRANK;
    int i = blockIdx.x * 256 + threadIdx.x;
    if (i < n_out) { split1(ow[i], g_outw_h, g_outw_l, i); return; }
    i -= n_out;
    if (i < n_xp)  { split1(xw[i], g_xpw_h, g_xpw_l, i); return; }
    i -= n_xp;
    if (i < n_dt)  { split1(dw[i], g_dtw_h, g_dtw_l, i); }
}

// ---------------- x_proj split-K reduce + dt hi/lo split ----------------
__global__ void dbc_reduce() {
    const int i = blockIdx.x * 256 + threadIdx.x;   // TOK*64
    float s = 0.f;
#pragma unroll
    for (int p = 0; p < KSPLIT; p++) s += g_dbcp[(long)p * TOK*64 + i];
    g_dbc[i] = s;
    const int col = i & 63;
    if (col < DTRANK) {
        const long di = (long)(i >> 6) * DTRANK + col;
        split1(s, g_dt_h, g_dt_l, di);
    }
}

// ---------------- rmsnorm: writes bf16 hi/lo ----------------
__global__ void rmsnorm_kernel(const float* __restrict__ w) {
    const int tkn = blockIdx.x;
    const float* xr = g_xbuf + (long)tkn * DMODEL;
    const int t = threadIdx.x;   // 128
    float v[4];
    float s = 0.f;
#pragma unroll
    for (int i = 0; i < 4; i++) { v[i] = xr[t + i*128]; s += v[i]*v[i]; }
#pragma unroll
    for (int off = 16; off; off >>= 1) s += __shfl_xor_sync(0xffffffffu, s, off);
    __shared__ float sh[4];
    if ((t & 31) == 0) sh[t >> 5] = s;
    __syncthreads();
    const float scale = rsqrtf((sh[0]+sh[1]+sh[2]+sh[3]) * (1.0f/DMODEL) + 1e-5f);
#pragma unroll
    for (int i = 0; i < 4; i++) {
        const float o = v[i] * scale * __ldg(&w[t + i*128]);
        split1(o, g_xn_h, g_xn_l, (long)tkn * DMODEL + t + i*128);
    }
}

// ---------------- causal dwconv(4) + silu, x4-vectorized ----------------
// each thread: 4 consecutive e channels of one token
__global__ void conv_silu_kernel(const float* __restrict__ wc, const float* __restrict__ bc) {
    const int idx = blockIdx.x * blockDim.x + threadIdx.x;  // TOK*ED/4
    const int e   = (idx << 2) & (ED - 1);
    const int tkn = idx >> 8;                               // (idx*4)>>10
    const int s   = tkn & (SEQ - 1);

    const float4 b4 = *(const float4*)(bc + e);
    float ax = b4.x, ay = b4.y, az = b4.z, aw = b4.w;

    // weights: wc[e+j][k] for j=0..3
    const float4 w0 = *(const float4*)(wc + (e+0)*DCONV);
    const float4 w1 = *(const float4*)(wc + (e+1)*DCONV);
    const float4 w2 = *(const float4*)(wc + (e+2)*DCONV);
    const float4 w3 = *(const float4*)(wc + (e+3)*DCONV);
    const float wk[4][4] = {{w0.x,w1.x,w2.x,w3.x}, {w0.y,w1.y,w2.y,w3.y},
                            {w0.z,w1.z,w2.z,w3.z}, {w0.w,w1.w,w2.w,w3.w}};

    const float* xb = g_xz + (long)tkn * (2*ED) + e;
#pragma unroll
    for (int k = 0; k < DCONV; k++) {
        const int ss = s - (DCONV - 1) + k;
        if (ss >= 0) {
            const float4 xv = *(const float4*)(xb + (long)(k - (DCONV - 1)) * (2*ED));
            ax += wk[k][0] * xv.x; ay += wk[k][1] * xv.y;
            az += wk[k][2] * xv.z; aw += wk[k][3] * xv.w;
        }
    }
    const float vx = ax / (1.f + __expf(-ax));
    const float vy = ay / (1.f + __expf(-ay));
    const float vz = az / (1.f + __expf(-az));
    const float vw = aw / (1.f + __expf(-aw));

    const long o = (long)tkn * ED + e;
    *(float4*)(g_xc + o) = make_float4(vx, vy, vz, vw);

    const bf16 hx = __float2bfloat16(vx), hy = __float2bfloat16(vy);
    const bf16 hz = __float2bfloat16(vz), hw = __float2bfloat16(vw);
    __nv_bfloat162* ph = (__nv_bfloat162*)(g_xc_h + o);
    ph[0] = __nv_bfloat162(hx, hy);
    ph[1] = __nv_bfloat162(hz, hw);
    __nv_bfloat162* pl = (__nv_bfloat162*)(g_xc_l + o);
    pl[0] = __nv_bfloat162(__float2bfloat16(vx - __bfloat162float(hx)),
                           __float2bfloat16(vy - __bfloat162float(hy)));
    pl[1] = __nv_bfloat162(__float2bfloat16(vz - __bfloat162float(hz)),
                           __float2bfloat16(vw - __bfloat162float(hw)));
}

// ---------------- chunked parallel selective scan, coalesced mapping ----------------
#define CHS 64
__global__ void __launch_bounds__(256) scan_kernel(const float* __restrict__ A_log,
                                                   const float* __restrict__ Dp) {
    __shared__ float sP[8][8][16], sH[8][8][16], sHin[8][8][16];

    const int cta = blockIdx.x;                 // 1024 CTAs
    const int b   = cta >> 7;
    const int e0  = (cta & 127) * 8;
    const int c   = threadIdx.x >> 5;
    const int lane= threadIdx.x & 31;
    const int el  = lane >> 2, sub = lane & 3;
    const int e   = e0 + el;

    float a[4];
#pragma unroll
    for (int j = 0; j < 4; j++)
        a[j] = -__expf(__ldg(&A_log[e * DSTATE + sub * 4 + j]));
    const float dpe = __ldg(&Dp[e]);

    const long r0 = (long)b * SEQ + c * CHS;
    const float* dptr = g_delta + r0 * ED + e;
    const float* xptr = g_xc    + r0 * ED + e;
    const float* zptr = g_xz    + r0 * (2*ED) + ED + e;
    const float* bcp  = g_dbc   + r0 * 64 + DTRANK + sub * 4;

    float P[4] = {1.f,1.f,1.f,1.f}, H[4] = {0.f,0.f,0.f,0.f};
    for (int s = 0; s < CHS; s++) {
        const float d  = dptr[(long)s * ED];
        const float xv = xptr[(long)s * ED];
        const float4 Bv = *(const float4*)(bcp + (long)s * 64);
        const float dx = d * xv;
        const float bx[4] = {Bv.x, Bv.y, Bv.z, Bv.w};
#pragma unroll
        for (int j = 0; j < 4; j++) {
            const float da = __expf(d * a[j]);
            H[j] = da * H[j] + dx * bx[j];
            P[j] *= da;
        }
    }
#pragma unroll
    for (int j = 0; j < 4; j++) {
        sP[c][el][sub*4 + j] = P[j];
        sH[c][el][sub*4 + j] = H[j];
    }
    __syncthreads();

    if (threadIdx.x < 128) {
        const int el2 = threadIdx.x >> 4, st = threadIdx.x & 15;
        float h = 0.f;
#pragma unroll
        for (int c2 = 0; c2 < 8; c2++) {
            sHin[c2][el2][st] = h;
            h = sP[c2][el2][st] * h + sH[c2][el2][st];
        }
    }
    __syncthreads();

    float h[4];
#pragma unroll
    for (int j = 0; j < 4; j++) h[j] = sHin[c][el][sub*4 + j];

    const long ybase = r0 * ED + e;
    for (int s = 0; s < CHS; s++) {
        const float d  = dptr[(long)s * ED];
        const float xv = xptr[(long)s * ED];
        const float4 Bv = *(const float4*)(bcp + (long)s * 64);
        const float4 Cv = *(const float4*)(bcp + (long)s * 64 + DSTATE);
        const float dx = d * xv;
        const float bx[4] = {Bv.x, Bv.y, Bv.z, Bv.w};
        const float cx[4] = {Cv.x, Cv.y, Cv.z, Cv.w};
        float acc = 0.f;
#pragma unroll
        for (int j = 0; j < 4; j++) {
            h[j] = __expf(d * a[j]) * h[j] + dx * bx[j];
            acc += h[j] * cx[j];
        }
        acc += __shfl_xor_sync(0xffffffffu, acc, 1);
        acc += __shfl_xor_sync(0xffffffffu, acc, 2);
        if (sub == 0) {
            const float z = zptr[(long)s * (2*ED)];
            const float y = (acc + dpe * xv) * (z / (1.f + __expf(-z)));
            split1(y, g_y_h, g_y_l, ybase + (long)s * ED);
        }
    }
}

// ---------------- final MLP head ----------------
__global__ void head_kernel(const float* __restrict__ w1, const float* __restrict__ b1,
                            const float* __restrict__ w2, const float* __restrict__ b2,
                            float* __restrict__ out) {
    const int b = blockIdx.x;
    const int j = threadIdx.x;  // 64
    const float* last = g_xbuf + ((long)b * SEQ + (SEQ - 1)) * DMODEL;
    const float* wr = w1 + (long)j * DMODEL;
    float s = 0.f;
    for (int c = 0; c < DMODEL; c++) s += last[c] * __ldg(&wr[c]);
    s = fmaxf(s + __ldg(&b1[j]), 0.f);
    __shared__ float sh[64];
    sh[j] = s * __ldg(&w2[j]);
    __syncthreads();
    if (j == 0) {
        float tot = 0.f;
        for (int k = 0; k < 64; k++) tot += sh[k];
        out[b] = tot + __ldg(&b2[0]);
    }
}

// ---------------- launch ----------------
extern "C" void kernel_launch(void* const* d_in, const int* in_sizes, int n_in,
                              void* d_out, int out_size) {
    const float* x         = (const float*)d_in[0];
    const float* norm_w    = (const float*)d_in[1];
    const float* in_proj_w = (const float*)d_in[2];
    const float* conv_w    = (const float*)d_in[3];
    const float* conv_b    = (const float*)d_in[4];
    const float* x_proj_w  = (const float*)d_in[5];
    const float* dt_proj_w = (const float*)d_in[6];
    const float* dt_proj_b = (const float*)d_in[7];
    const float* A_log     = (const float*)d_in[8];
    const float* Dp        = (const float*)d_in[9];
    const float* out_proj_w= (const float*)d_in[10];
    const float* w1        = (const float*)d_in[11];
    const float* b1        = (const float*)d_in[12];
    const float* w2        = (const float*)d_in[13];
    const float* b2        = (const float*)d_in[14];

    float *p_xbuf, *p_xz, *p_dbcp, *p_delta;
    cudaGetSymbolAddress((void**)&p_xbuf,  g_xbuf);
    cudaGetSymbolAddress((void**)&p_xz,    g_xz);
    cudaGetSymbolAddress((void**)&p_dbcp,  g_dbcp);
    cudaGetSymbolAddress((void**)&p_delta, g_delta);

    bf16 *p_xn_h, *p_xn_l, *p_xc_h, *p_xc_l, *p_y_h, *p_y_l, *p_dt_h, *p_dt_l;
    bf16 *p_inw_h, *p_inw_l, *p_outw_h, *p_outw_l, *p_xpw_h, *p_xpw_l, *p_dtw_h, *p_dtw_l;
    cudaGetSymbolAddress((void**)&p_xn_h, g_xn_h);   cudaGetSymbolAddress((void**)&p_xn_l, g_xn_l);
    cudaGetSymbolAddress((void**)&p_xc_h, g_xc_h);   cudaGetSymbolAddress((void**)&p_xc_l, g_xc_l);
    cudaGetSymbolAddress((void**)&p_y_h,  g_y_h);    cudaGetSymbolAddress((void**)&p_y_l,  g_y_l);
    cudaGetSymbolAddress((void**)&p_dt_h, g_dt_h);   cudaGetSymbolAddress((void**)&p_dt_l, g_dt_l);
    cudaGetSymbolAddress((void**)&p_inw_h, g_inw_h); cudaGetSymbolAddress((void**)&p_inw_l, g_inw_l);
    cudaGetSymbolAddress((void**)&p_outw_h, g_outw_h); cudaGetSymbolAddress((void**)&p_outw_l, g_outw_l);
    cudaGetSymbolAddress((void**)&p_xpw_h, g_xpw_h); cudaGetSymbolAddress((void**)&p_xpw_l, g_xpw_l);
    cudaGetSymbolAddress((void**)&p_dtw_h, g_dtw_h); cudaGetSymbolAddress((void**)&p_dtw_l, g_dtw_l);

    cudaFuncSetAttribute(hmma_gemm<0>, cudaFuncAttributeMaxDynamicSharedMemorySize, GSMEM);
    cudaFuncSetAttribute(hmma_gemm<1>, cudaFuncAttributeMaxDynamicSharedMemorySize, GSMEM);
    cudaFuncSetAttribute(hmma_gemm<2>, cudaFuncAttributeMaxDynamicSharedMemorySize, GSMEM);

    // ---- weight conversion (2 kernels -> in_proj at profile index 3) ----
    {
        const int n_in_w = NLAYERS*2*ED*DMODEL;
        cvt_inw<<<(n_in_w + 255)/256, 256>>>(in_proj_w);
        const int n_rest = NLAYERS*DMODEL*ED + NLAYERS*64*ED + NLAYERS*ED*DTRANK;
        cvt_rest<<<(n_rest + 255)/256, 256>>>(out_proj_w, x_proj_w, dt_proj_w);
    }

    // residual stream = input x
    cudaMemcpyAsync(p_xbuf, x, sizeof(float) * (size_t)TOK * DMODEL,
                    cudaMemcpyDeviceToDevice, 0);

    for (int l = 0; l < NLAYERS; l++) {
        // 1) rmsnorm -> xn hi/lo
        rmsnorm_kernel<<<TOK, 128>>>(norm_w + (long)l * DMODEL);

        // 2) in_proj: [4096,512]x[2048,512]^T -> xz fp32   (profile index 3, layer 0)
        hmma_gemm<0><<<dim3(2*ED/64, TOK/128, 1), 256, GSMEM>>>(
            p_xn_h, p_xn_l, DMODEL,
            p_inw_h + (long)l * 2*ED * DMODEL, p_inw_l + (long)l * 2*ED * DMODEL, DMODEL,
            p_xz, 2*ED, DMODEL, 0, nullptr);

        // 3) conv + silu (x4 vectorized) -> xc fp32 + hi/lo
        conv_silu_kernel<<<TOK * ED / 4 / 256, 256>>>(conv_w + (long)l * ED * DCONV,
                                                      conv_b + (long)l * ED);

        // 4) x_proj split-K: [4096,1024]x[64,1024]^T -> 8 partials (K=128 each)
        hmma_gemm<0><<<dim3(1, TOK/128, KSPLIT), 256, GSMEM>>>(
            p_xc_h, p_xc_l, ED,
            p_xpw_h + (long)l * 64 * ED, p_xpw_l + (long)l * 64 * ED, ED,
            p_dbcp, 64, ED/KSPLIT, (long)TOK*64, nullptr);

        // 4b) reduce partials -> dbc + dt hi/lo split
        dbc_reduce<<<TOK * 64 / 256, 256>>>();

        // 5) dt_proj + softplus: [4096,32]x[1024,32]^T -> delta
        hmma_gemm<1><<<dim3(ED/64, TOK/128, 1), 256, GSMEM>>>(
            p_dt_h, p_dt_l, DTRANK,
            p_dtw_h + (long)l * ED * DTRANK, p_dtw_l + (long)l * ED * DTRANK, DTRANK,
            p_delta, ED, DTRANK, 0, dt_proj_b + (long)l * ED);

        // 6) coalesced chunked parallel scan -> y hi/lo
        scan_kernel<<<BATCH * ED / 8, 256>>>(A_log + (long)l * ED * DSTATE,
                                             Dp + (long)l * ED);

        // 7) out_proj + residual: [4096,1024]x[512,1024]^T += xbuf
        hmma_gemm<2><<<dim3(DMODEL/64, TOK/128, 1), 256, GSMEM>>>(
            p_y_h, p_y_l, ED,
            p_outw_h + (long)l * DMODEL * ED, p_outw_l + (long)l * DMODEL * ED, ED,
            p_xbuf, DMODEL, ED, 0, nullptr);
    }

    head_kernel<<<BATCH, 64>>>(w1, b1, w2, b2, (float*)d_out);
}

// round 17
// speedup vs baseline: 1.0429x; 1.0429x over previous
#include <cuda_runtime.h>
#include <cuda_bf16.h>
#include <cstdint>

// ---------------- problem constants ----------------
#define NLAYERS 4
#define BATCH   8
#define SEQ     512
#define DMODEL  512
#define ED      1024
#define DSTATE  16
#define DTRANK  32
#define DCONV   4
#define TOK     (BATCH*SEQ)   // 4096
#define KSPLIT  8             // x_proj K-slices
#define KSPLIT_O 4            // out_proj K-slices

typedef __nv_bfloat16 bf16;

// ---------------- scratch (device globals; no allocation) ----------------
__device__ __align__(16) float g_xbuf [TOK*DMODEL];     // residual stream
__device__ __align__(16) float g_xz   [TOK*2*ED];       // in_proj out (xb|z)
__device__ __align__(16) float g_xc   [TOK*ED];         // conv+silu (fp32 for scan)
__device__ __align__(16) float g_dbc  [TOK*64];         // x_proj out (dt|B|C)
__device__ __align__(16) float g_dbcp [KSPLIT*TOK*64];  // x_proj split-K partials
__device__ __align__(16) float g_outp [KSPLIT_O*TOK*DMODEL]; // out_proj partials
__device__ __align__(16) float g_delta[TOK*ED];         // softplus(dt_proj)

// bf16 split activations
__device__ __align__(16) bf16 g_xn_h[TOK*DMODEL],  g_xn_l[TOK*DMODEL];
__device__ __align__(16) bf16 g_xc_h[TOK*ED],      g_xc_l[TOK*ED];
__device__ __align__(16) bf16 g_y_h [TOK*ED],      g_y_l [TOK*ED];
__device__ __align__(16) bf16 g_dt_h[TOK*DTRANK],  g_dt_l[TOK*DTRANK];

// bf16 split weights
__device__ __align__(16) bf16 g_inw_h[NLAYERS*2*ED*DMODEL], g_inw_l[NLAYERS*2*ED*DMODEL];
__device__ __align__(16) bf16 g_outw_h[NLAYERS*DMODEL*ED],  g_outw_l[NLAYERS*DMODEL*ED];
__device__ __align__(16) bf16 g_xpw_h[NLAYERS*64*ED],       g_xpw_l[NLAYERS*64*ED];
__device__ __align__(16) bf16 g_dtw_h[NLAYERS*ED*DTRANK],   g_dtw_l[NLAYERS*ED*DTRANK];

// ---------------- HMMA m16n8k16 bf16 + ldmatrix ----------------
__device__ __forceinline__ void mma16816(float* c, const uint32_t* a, const uint32_t* b) {
    asm volatile(
        "mma.sync.aligned.m16n8k16.row.col.f32.bf16.bf16.f32 "
        "{%0,%1,%2,%3}, {%4,%5,%6,%7}, {%8,%9}, {%0,%1,%2,%3};"
        : "+f"(c[0]), "+f"(c[1]), "+f"(c[2]), "+f"(c[3])
        : "r"(a[0]), "r"(a[1]), "r"(a[2]), "r"(a[3]), "r"(b[0]), "r"(b[1]));
}
__device__ __forceinline__ void ldsm_x4(uint32_t* r, uint32_t addr) {
    asm volatile("ldmatrix.sync.aligned.m8n8.x4.shared.b16 {%0,%1,%2,%3}, [%4];"
        : "=r"(r[0]), "=r"(r[1]), "=r"(r[2]), "=r"(r[3]) : "r"(addr));
}
__device__ __forceinline__ void ldsm_x2(uint32_t* r, uint32_t addr) {
    asm volatile("ldmatrix.sync.aligned.m8n8.x2.shared.b16 {%0,%1}, [%2];"
        : "=r"(r[0]), "=r"(r[1]) : "r"(addr));
}
__device__ __forceinline__ void cp16(uint32_t smem_dst, const void* gsrc) {
    asm volatile("cp.async.cg.shared.global [%0], [%1], 16;" :: "r"(smem_dst), "l"(gsrc));
}
#define CP_COMMIT() asm volatile("cp.async.commit_group;" ::: "memory")
#define CP_WAIT(N)  asm volatile("cp.async.wait_group %0;" :: "n"(N) : "memory")

// ---------------- split-bf16 HMMA GEMM, 2-stage cp.async, ldmatrix ----------------
// C[M=4096, N](fp32) = [Ah+Al][M,Ktot] * [Bh+Bl][N,Ktot]^T
// blockIdx.z = K-slice (length K); C advances czs per slice.
// EPI: 0 store, 1 softplus(acc+bias), 2 residual +=
#define SPAD 40
#define ASZ  (128*SPAD)
#define BSZ  (64*SPAD)
#define STG  (2*ASZ + 2*BSZ)
#define NSTG 2
#define GSMEM (NSTG*STG*2)           // 61440 bytes -> 3 CTAs/SM (regs capped)

template<int EPI>
__global__ void __launch_bounds__(256, 3) hmma_gemm(
    const bf16* __restrict__ Ah, const bf16* __restrict__ Al, int lda,
    const bf16* __restrict__ Bh, const bf16* __restrict__ Bl, int ldb,
    float* __restrict__ C, int ldc, int K, long czs,
    const float* __restrict__ bias)
{
    extern __shared__ bf16 sm[];

    const int tid = threadIdx.x;
    const int wid = tid >> 5, lid = tid & 31;
    const int t = lid & 3;
    const int wm = wid >> 1, wn = wid & 1;
    const int mb = blockIdx.y * 128;
    const int nb = blockIdx.x * 64;
    const int koff = blockIdx.z * K;
    C += (long)blockIdx.z * czs;

    const int arow = tid >> 2, aseg = tid & 3;
    const int a_r = wm*32 + (lid & 15);
    const int a_c = (lid >> 4) * 8;
    const int b_r = wn*32 + (lid & 7);
    const int b_c = ((lid >> 3) & 1) * 8;

    const uint32_t smbase = (uint32_t)__cvta_generic_to_shared(sm);

    float c[2][4][4];
#pragma unroll
    for (int mi = 0; mi < 2; mi++)
#pragma unroll
        for (int ni = 0; ni < 4; ni++)
#pragma unroll
            for (int k = 0; k < 4; k++) c[mi][ni][k] = 0.f;

    const int nch = K >> 5;

    auto load_stage = [&](int ch, int st) {
        const int k0 = koff + (ch << 5);
        const uint32_t s0 = smbase + (uint32_t)(st * STG) * 2u;
#pragma unroll
        for (int i = 0; i < 2; i++) {
            const int row = arow + i*64;
            const uint32_t d = s0 + (uint32_t)(row*SPAD + aseg*8) * 2u;
            const long gi = (long)(mb + row) * lda + k0 + aseg*8;
            cp16(d,            Ah + gi);
            cp16(d + ASZ*2u,   Al + gi);
        }
        {
            const uint32_t d = s0 + (uint32_t)(2*ASZ + arow*SPAD + aseg*8) * 2u;
            const long gi = (long)(nb + arow) * ldb + k0 + aseg*8;
            cp16(d,            Bh + gi);
            cp16(d + BSZ*2u,   Bl + gi);
        }
    };

    load_stage(0, 0);
    CP_COMMIT();

    for (int ch = 0; ch < nch; ch++) {
        const int st = ch & 1;
        if (ch + 1 < nch) {
            load_stage(ch + 1, st ^ 1);
            CP_COMMIT();
            CP_WAIT(1);
        } else {
            CP_WAIT(0);
        }
        __syncthreads();

        const uint32_t sA_h = smbase + (uint32_t)(st * STG) * 2u;
        const uint32_t sA_l = sA_h + ASZ*2u;
        const uint32_t sB_h = sA_h + 2u*ASZ*2u;
        const uint32_t sB_l = sB_h + BSZ*2u;

#pragma unroll
        for (int kk = 0; kk < 2; kk++) {
            const int kb = kk * 16;
            uint32_t ah[2][4], al[2][4], bh[4][2], bl[4][2];
#pragma unroll
            for (int mi = 0; mi < 2; mi++) {
                const uint32_t off = (uint32_t)((a_r + mi*16)*SPAD + kb + a_c) * 2u;
                ldsm_x4(ah[mi], sA_h + off);
                ldsm_x4(al[mi], sA_l + off);
            }
#pragma unroll
            for (int ni = 0; ni < 4; ni++) {
                const uint32_t off = (uint32_t)((b_r + ni*8)*SPAD + kb + b_c) * 2u;
                ldsm_x2(bh[ni], sB_h + off);
                ldsm_x2(bl[ni], sB_l + off);
            }
#pragma unroll
            for (int mi = 0; mi < 2; mi++)
#pragma unroll
                for (int ni = 0; ni < 4; ni++) {
                    mma16816(c[mi][ni], ah[mi], bh[ni]);
                    mma16816(c[mi][ni], ah[mi], bl[ni]);
                    mma16816(c[mi][ni], al[mi], bh[ni]);
                }
        }
        __syncthreads();
    }

    // ---- epilogue ----
    const int g = lid >> 2;
#pragma unroll
    for (int mi = 0; mi < 2; mi++) {
        const int row0 = mb + wm*32 + mi*16 + g;
#pragma unroll
        for (int ni = 0; ni < 4; ni++) {
            const int col = nb + wn*32 + ni*8 + 2*t;
#pragma unroll
            for (int h = 0; h < 2; h++) {
                float v0 = c[mi][ni][2*h + 0];
                float v1 = c[mi][ni][2*h + 1];
                const int row = row0 + h*8;
                float* Cr = C + (long)row * ldc + col;
                if (EPI == 1) {
                    v0 += __ldg(&bias[col + 0]);
                    v1 += __ldg(&bias[col + 1]);
                    v0 = fmaxf(v0, 0.f) + log1pf(__expf(-fabsf(v0)));
                    v1 = fmaxf(v1, 0.f) + log1pf(__expf(-fabsf(v1)));
                } else if (EPI == 2) {
                    const float2 old = *(const float2*)Cr;
                    v0 += old.x; v1 += old.y;
                }
                *(float2*)Cr = make_float2(v0, v1);
            }
        }
    }
}

// ---------------- fp32 -> bf16 hi/lo split ----------------
__device__ __forceinline__ void split1(float v, bf16* h, bf16* l, long i) {
    const bf16 hv = __float2bfloat16(v);
    h[i] = hv;
    l[i] = __float2bfloat16(v - __bfloat162float(hv));
}
// in_proj weights converter (kernel 0)
__global__ void cvt_inw(const float* __restrict__ iw) {
    const int i = blockIdx.x * 256 + threadIdx.x;
    if (i < NLAYERS*2*ED*DMODEL) split1(iw[i], g_inw_h, g_inw_l, i);
}
// remaining weights converter (kernel 1)
__global__ void cvt_rest(const float* __restrict__ ow, const float* __restrict__ xw,
                         const float* __restrict__ dw) {
    const int n_out = NLAYERS*DMODEL*ED;
    const int n_xp  = NLAYERS*64*ED;
    const int n_dt  = NLAYERS*ED*DTRANK;
    int i = blockIdx.x * 256 + threadIdx.x;
    if (i < n_out) { split1(ow[i], g_outw_h, g_outw_l, i); return; }
    i -= n_out;
    if (i < n_xp)  { split1(xw[i], g_xpw_h, g_xpw_l, i); return; }
    i -= n_xp;
    if (i < n_dt)  { split1(dw[i], g_dtw_h, g_dtw_l, i); }
}

// ---------------- x_proj split-K reduce + dt hi/lo split ----------------
__global__ void dbc_reduce() {
    const int i = blockIdx.x * 256 + threadIdx.x;   // TOK*64
    float s = 0.f;
#pragma unroll
    for (int p = 0; p < KSPLIT; p++) s += g_dbcp[(long)p * TOK*64 + i];
    g_dbc[i] = s;
    const int col = i & 63;
    if (col < DTRANK) {
        const long di = (long)(i >> 6) * DTRANK + col;
        split1(s, g_dt_h, g_dt_l, di);
    }
}

// ---------------- out_proj split-K reduce + residual add ----------------
__global__ void out_reduce() {
    const int i = blockIdx.x * 256 + threadIdx.x;   // TOK*DMODEL
    float s = g_xbuf[i];
#pragma unroll
    for (int p = 0; p < KSPLIT_O; p++) s += g_outp[(long)p * TOK*DMODEL + i];
    g_xbuf[i] = s;
}

// ---------------- rmsnorm: writes bf16 hi/lo ----------------
__global__ void rmsnorm_kernel(const float* __restrict__ w) {
    const int tkn = blockIdx.x;
    const float* xr = g_xbuf + (long)tkn * DMODEL;
    const int t = threadIdx.x;   // 128
    float v[4];
    float s = 0.f;
#pragma unroll
    for (int i = 0; i < 4; i++) { v[i] = xr[t + i*128]; s += v[i]*v[i]; }
#pragma unroll
    for (int off = 16; off; off >>= 1) s += __shfl_xor_sync(0xffffffffu, s, off);
    __shared__ float sh[4];
    if ((t & 31) == 0) sh[t >> 5] = s;
    __syncthreads();
    const float scale = rsqrtf((sh[0]+sh[1]+sh[2]+sh[3]) * (1.0f/DMODEL) + 1e-5f);
#pragma unroll
    for (int i = 0; i < 4; i++) {
        const float o = v[i] * scale * __ldg(&w[t + i*128]);
        split1(o, g_xn_h, g_xn_l, (long)tkn * DMODEL + t + i*128);
    }
}

// ---------------- causal dwconv(4) + silu (scalar, measured 19us) ----------------
__global__ void conv_silu_kernel(const float* __restrict__ wc, const float* __restrict__ bc) {
    const int idx = blockIdx.x * blockDim.x + threadIdx.x;  // TOK*ED
    const int e   = idx & (ED - 1);
    const int tkn = idx >> 10;
    const int s   = tkn & (SEQ - 1);
    const float* xb = g_xz + (long)tkn * (2*ED) + e;
    float acc = __ldg(&bc[e]);
    const float* w4 = wc + e * DCONV;
#pragma unroll
    for (int k = 0; k < DCONV; k++) {
        const int ss = s - (DCONV - 1) + k;
        if (ss >= 0) acc += __ldg(&w4[k]) * xb[(long)(k - (DCONV - 1)) * (2*ED)];
    }
    const float v = acc / (1.f + __expf(-acc));
    const long o = (long)tkn * ED + e;
    g_xc[o] = v;
    split1(v, g_xc_h, g_xc_l, o);
}

// ---------------- chunked parallel selective scan, coalesced mapping ----------------
#define CHS 64
__global__ void __launch_bounds__(256) scan_kernel(const float* __restrict__ A_log,
                                                   const float* __restrict__ Dp) {
    __shared__ float sP[8][8][16], sH[8][8][16], sHin[8][8][16];

    const int cta = blockIdx.x;                 // 1024 CTAs
    const int b   = cta >> 7;
    const int e0  = (cta & 127) * 8;
    const int c   = threadIdx.x >> 5;
    const int lane= threadIdx.x & 31;
    const int el  = lane >> 2, sub = lane & 3;
    const int e   = e0 + el;

    float a[4];
#pragma unroll
    for (int j = 0; j < 4; j++)
        a[j] = -__expf(__ldg(&A_log[e * DSTATE + sub * 4 + j]));
    const float dpe = __ldg(&Dp[e]);

    const long r0 = (long)b * SEQ + c * CHS;
    const float* dptr = g_delta + r0 * ED + e;
    const float* xptr = g_xc    + r0 * ED + e;
    const float* zptr = g_xz    + r0 * (2*ED) + ED + e;
    const float* bcp  = g_dbc   + r0 * 64 + DTRANK + sub * 4;

    float P[4] = {1.f,1.f,1.f,1.f}, H[4] = {0.f,0.f,0.f,0.f};
    for (int s = 0; s < CHS; s++) {
        const float d  = dptr[(long)s * ED];
        const float xv = xptr[(long)s * ED];
        const float4 Bv = *(const float4*)(bcp + (long)s * 64);
        const float dx = d * xv;
        const float bx[4] = {Bv.x, Bv.y, Bv.z, Bv.w};
#pragma unroll
        for (int j = 0; j < 4; j++) {
            const float da = __expf(d * a[j]);
            H[j] = da * H[j] + dx * bx[j];
            P[j] *= da;
        }
    }
#pragma unroll
    for (int j = 0; j < 4; j++) {
        sP[c][el][sub*4 + j] = P[j];
        sH[c][el][sub*4 + j] = H[j];
    }
    __syncthreads();

    if (threadIdx.x < 128) {
        const int el2 = threadIdx.x >> 4, st = threadIdx.x & 15;
        float h = 0.f;
#pragma unroll
        for (int c2 = 0; c2 < 8; c2++) {
            sHin[c2][el2][st] = h;
            h = sP[c2][el2][st] * h + sH[c2][el2][st];
        }
    }
    __syncthreads();

    float h[4];
#pragma unroll
    for (int j = 0; j < 4; j++) h[j] = sHin[c][el][sub*4 + j];

    const long ybase = r0 * ED + e;
    for (int s = 0; s < CHS; s++) {
        const float d  = dptr[(long)s * ED];
        const float xv = xptr[(long)s * ED];
        const float4 Bv = *(const float4*)(bcp + (long)s * 64);
        const float4 Cv = *(const float4*)(bcp + (long)s * 64 + DSTATE);
        const float dx = d * xv;
        const float bx[4] = {Bv.x, Bv.y, Bv.z, Bv.w};
        const float cx[4] = {Cv.x, Cv.y, Cv.z, Cv.w};
        float acc = 0.f;
#pragma unroll
        for (int j = 0; j < 4; j++) {
            h[j] = __expf(d * a[j]) * h[j] + dx * bx[j];
            acc += h[j] * cx[j];
        }
        acc += __shfl_xor_sync(0xffffffffu, acc, 1);
        acc += __shfl_xor_sync(0xffffffffu, acc, 2);
        if (sub == 0) {
            const float z = zptr[(long)s * (2*ED)];
            const float y = (acc + dpe * xv) * (z / (1.f + __expf(-z)));
            split1(y, g_y_h, g_y_l, ybase + (long)s * ED);
        }
    }
}

// ---------------- final MLP head ----------------
__global__ void head_kernel(const float* __restrict__ w1, const float* __restrict__ b1,
                            const float* __restrict__ w2, const float* __restrict__ b2,
                            float* __restrict__ out) {
    const int b = blockIdx.x;
    const int j = threadIdx.x;  // 64
    const float* last = g_xbuf + ((long)b * SEQ + (SEQ - 1)) * DMODEL;
    const float* wr = w1 + (long)j * DMODEL;
    float s = 0.f;
    for (int c = 0; c < DMODEL; c++) s += last[c] * __ldg(&wr[c]);
    s = fmaxf(s + __ldg(&b1[j]), 0.f);
    __shared__ float sh[64];
    sh[j] = s * __ldg(&w2[j]);
    __syncthreads();
    if (j == 0) {
        float tot = 0.f;
        for (int k = 0; k < 64; k++) tot += sh[k];
        out[b] = tot + __ldg(&b2[0]);
    }
}

// ---------------- launch ----------------
extern "C" void kernel_launch(void* const* d_in, const int* in_sizes, int n_in,
                              void* d_out, int out_size) {
    const float* x         = (const float*)d_in[0];
    const float* norm_w    = (const float*)d_in[1];
    const float* in_proj_w = (const float*)d_in[2];
    const float* conv_w    = (const float*)d_in[3];
    const float* conv_b    = (const float*)d_in[4];
    const float* x_proj_w  = (const float*)d_in[5];
    const float* dt_proj_w = (const float*)d_in[6];
    const float* dt_proj_b = (const float*)d_in[7];
    const float* A_log     = (const float*)d_in[8];
    const float* Dp        = (const float*)d_in[9];
    const float* out_proj_w= (const float*)d_in[10];
    const float* w1        = (const float*)d_in[11];
    const float* b1        = (const float*)d_in[12];
    const float* w2        = (const float*)d_in[13];
    const float* b2        = (const float*)d_in[14];

    float *p_xbuf, *p_xz, *p_dbcp, *p_outp, *p_delta;
    cudaGetSymbolAddress((void**)&p_xbuf,  g_xbuf);
    cudaGetSymbolAddress((void**)&p_xz,    g_xz);
    cudaGetSymbolAddress((void**)&p_dbcp,  g_dbcp);
    cudaGetSymbolAddress((void**)&p_outp,  g_outp);
    cudaGetSymbolAddress((void**)&p_delta, g_delta);

    bf16 *p_xn_h, *p_xn_l, *p_xc_h, *p_xc_l, *p_y_h, *p_y_l, *p_dt_h, *p_dt_l;
    bf16 *p_inw_h, *p_inw_l, *p_outw_h, *p_outw_l, *p_xpw_h, *p_xpw_l, *p_dtw_h, *p_dtw_l;
    cudaGetSymbolAddress((void**)&p_xn_h, g_xn_h);   cudaGetSymbolAddress((void**)&p_xn_l, g_xn_l);
    cudaGetSymbolAddress((void**)&p_xc_h, g_xc_h);   cudaGetSymbolAddress((void**)&p_xc_l, g_xc_l);
    cudaGetSymbolAddress((void**)&p_y_h,  g_y_h);    cudaGetSymbolAddress((void**)&p_y_l,  g_y_l);
    cudaGetSymbolAddress((void**)&p_dt_h, g_dt_h);   cudaGetSymbolAddress((void**)&p_dt_l, g_dt_l);
    cudaGetSymbolAddress((void**)&p_inw_h, g_inw_h); cudaGetSymbolAddress((void**)&p_inw_l, g_inw_l);
    cudaGetSymbolAddress((void**)&p_outw_h, g_outw_h); cudaGetSymbolAddress((void**)&p_outw_l, g_outw_l);
    cudaGetSymbolAddress((void**)&p_xpw_h, g_xpw_h); cudaGetSymbolAddress((void**)&p_xpw_l, g_xpw_l);
    cudaGetSymbolAddress((void**)&p_dtw_h, g_dtw_h); cudaGetSymbolAddress((void**)&p_dtw_l, g_dtw_l);

    cudaFuncSetAttribute(hmma_gemm<0>, cudaFuncAttributeMaxDynamicSharedMemorySize, GSMEM);
    cudaFuncSetAttribute(hmma_gemm<1>, cudaFuncAttributeMaxDynamicSharedMemorySize, GSMEM);
    cudaFuncSetAttribute(hmma_gemm<2>, cudaFuncAttributeMaxDynamicSharedMemorySize, GSMEM);

    // ---- weight conversion (2 kernels -> in_proj at profile index 3) ----
    {
        const int n_in_w = NLAYERS*2*ED*DMODEL;
        cvt_inw<<<(n_in_w + 255)/256, 256>>>(in_proj_w);
        const int n_rest = NLAYERS*DMODEL*ED + NLAYERS*64*ED + NLAYERS*ED*DTRANK;
        cvt_rest<<<(n_rest + 255)/256, 256>>>(out_proj_w, x_proj_w, dt_proj_w);
    }

    // residual stream = input x
    cudaMemcpyAsync(p_xbuf, x, sizeof(float) * (size_t)TOK * DMODEL,
                    cudaMemcpyDeviceToDevice, 0);

    for (int l = 0; l < NLAYERS; l++) {
        // 1) rmsnorm -> xn hi/lo
        rmsnorm_kernel<<<TOK, 128>>>(norm_w + (long)l * DMODEL);

        // 2) in_proj: [4096,512]x[2048,512]^T -> xz fp32   (profile index 3, layer 0)
        hmma_gemm<0><<<dim3(2*ED/64, TOK/128, 1), 256, GSMEM>>>(
            p_xn_h, p_xn_l, DMODEL,
            p_inw_h + (long)l * 2*ED * DMODEL, p_inw_l + (long)l * 2*ED * DMODEL, DMODEL,
            p_xz, 2*ED, DMODEL, 0, nullptr);

        // 3) conv + silu -> xc fp32 + hi/lo
        conv_silu_kernel<<<TOK * ED / 256, 256>>>(conv_w + (long)l * ED * DCONV,
                                                  conv_b + (long)l * ED);

        // 4) x_proj split-K: [4096,1024]x[64,1024]^T -> 8 partials (K=128 each)
        hmma_gemm<0><<<dim3(1, TOK/128, KSPLIT), 256, GSMEM>>>(
            p_xc_h, p_xc_l, ED,
            p_xpw_h + (long)l * 64 * ED, p_xpw_l + (long)l * 64 * ED, ED,
            p_dbcp, 64, ED/KSPLIT, (long)TOK*64, nullptr);

        // 4b) reduce partials -> dbc + dt hi/lo split
        dbc_reduce<<<TOK * 64 / 256, 256>>>();

        // 5) dt_proj + softplus: [4096,32]x[1024,32]^T -> delta
        hmma_gemm<1><<<dim3(ED/64, TOK/128, 1), 256, GSMEM>>>(
            p_dt_h, p_dt_l, DTRANK,
            p_dtw_h + (long)l * ED * DTRANK, p_dtw_l + (long)l * ED * DTRANK, DTRANK,
            p_delta, ED, DTRANK, 0, dt_proj_b + (long)l * ED);

        // 6) coalesced chunked parallel scan -> y hi/lo
        scan_kernel<<<BATCH * ED / 8, 256>>>(A_log + (long)l * ED * DSTATE,
                                             Dp + (long)l * ED);

        // 7) out_proj split-K: [4096,1024]x[512,1024]^T -> 4 partials (K=256 each)
        hmma_gemm<0><<<dim3(DMODEL/64, TOK/128, KSPLIT_O), 256, GSMEM>>>(
            p_y_h, p_y_l, ED,
            p_outw_h + (long)l * DMODEL * ED, p_outw_l + (long)l * DMODEL * ED, ED,
            p_outp, DMODEL, ED/KSPLIT_O, (long)TOK*DMODEL, nullptr);

        // 7b) reduce partials + residual -> xbuf
        out_reduce<<<TOK * DMODEL / 256, 256>>>();
    }

    head_kernel<<<BATCH, 64>>>(w1, b1, w2, b2, (float*)d_out);
}